// round 7
// baseline (speedup 1.0000x reference)
#include <cuda_runtime.h>
#include <math.h>

#define K 128
#define E 4096
#define M 512
#define NUM_UPDATE 3
#define THRESHOLD 0.05f
#define HOT 8
#define MAXNZ 32
#define KB 2                    // k's per big block
#define NBLK 16                 // e-chunks in big grid (256 e per block)
#define NB_TOTAL (NBLK * (K / KB))   // 1024 blocks
#define NBLK1 16                // init1 e-chunks (256 e per block)

// ---------------- device scratch ----------------
__device__ __align__(16) unsigned char g_nzpk[E * MAXNZ];
__device__ unsigned char g_cnt[E];
__device__ float4 g_cc[E];                    // (c0, c1, score, 1/d) per e
__device__ float  g_bz[E];                    // beta2 * Zc
__device__ float2 g_a12[(size_t)K * E];       // (uw*beta1, uw*bz)
__device__ float  g_Bc[(size_t)K * E * HOT];  // gathered B, diag/pad zeroed
__device__ float  g_u[K];
__device__ int    g_upd[K];
__device__ float  g_partial[K * NBLK];
__device__ unsigned g_done[NUM_UPDATE];

__device__ __forceinline__ float sigm_neg(float x) {
    return __fdividef(1.0f, 1.0f + __expf(x));  // sigmoid(-x)
}

// ---------------- init0: nz lists, per-e constants, u0, upd ----------------
// grid = E/8 = 512 blocks of 256 (warp per e)
__global__ void init0_kernel(const float* __restrict__ q_kn,
                             const float* __restrict__ U,
                             const int* __restrict__ stu_id,
                             const int* __restrict__ kn_id,
                             const float* __restrict__ gamma_c,
                             const float* __restrict__ dd,
                             const float* __restrict__ score,
                             const float* __restrict__ beta2,
                             const float* __restrict__ gs,
                             const float* __restrict__ A_emb) {
    int tid = threadIdx.x;
    int w = tid >> 5, l = tid & 31;
    int e = blockIdx.x * 8 + w;

    int base = 0;
#pragma unroll
    for (int r = 0; r < 4; r++) {
        int j = r * 32 + l;
        float q = q_kn[(size_t)e * K + j];
        unsigned m = __ballot_sync(0xFFFFFFFFu, q != 0.0f);
        if (q != 0.0f) {
            int pos = base + __popc(m & ((1u << l) - 1u));
            if (pos < MAXNZ) g_nzpk[e * MAXNZ + pos] = (unsigned char)j;
        }
        base += __popc(m);
    }
    if (l == 0) {
        g_cnt[e] = (unsigned char)(base < MAXNZ ? base : MAXNZ);
        float invd = 1.0f / dd[e];
        float sc   = score[e];
        float x  = (gamma_c[e] * invd) * (sc - 0.5f);
        g_bz[e]  = beta2[e] * (sigm_neg(x) - 0.5f);
        float c0 = A_emb[3 * e + 0] * (1.0f - gs[2 * e + 0])
                 + A_emb[3 * e + 1] * (1.0f - gs[2 * e + 1]);
        float c1 = A_emb[3 * e + 2];
        g_cc[e] = make_float4(c0, c1, sc, invd);
    }

    if (blockIdx.x == 0) {
        if (tid < NUM_UPDATE) g_done[tid] = 0u;
        if (tid < K) {
            g_u[tid] = U[(size_t)stu_id[0] * K + tid];
            g_upd[tid] = 0;
        }
        __syncthreads();
        if (tid < K) {
            int kn = kn_id[tid];
            if (kn >= 0 && kn < K) g_upd[kn] = 1;
        }
    }
}

// ---------------- init0b: a12 = (uw*beta1, uw*bz), vectorized ----------------
// must run after init0 (reads g_bz)
__global__ void init0b_kernel(const float* __restrict__ beta1,
                              const float* __restrict__ W,
                              const float* __restrict__ user) {
    int i4 = blockIdx.x * blockDim.x + threadIdx.x;   // float4 index
    const int N4 = K * E / 4;
    for (; i4 < N4; i4 += gridDim.x * blockDim.x) {
        float4 b = ((const float4*)beta1)[i4];
        float4 w = ((const float4*)W)[i4];
        float4 u = ((const float4*)user)[i4];
        int i = i4 * 4;
        float bz0 = g_bz[(i + 0) & (E - 1)];
        float bz1 = g_bz[(i + 1) & (E - 1)];
        float bz2 = g_bz[(i + 2) & (E - 1)];
        float bz3 = g_bz[(i + 3) & (E - 1)];
        float uw0 = u.x * w.x, uw1 = u.y * w.y, uw2 = u.z * w.z, uw3 = u.w * w.w;
        float2* dst = g_a12 + i;
        dst[0] = make_float2(uw0 * b.x, uw0 * bz0);
        dst[1] = make_float2(uw1 * b.y, uw1 * bz1);
        dst[2] = make_float2(uw2 * b.z, uw2 * bz2);
        dst[3] = make_float2(uw3 * b.w, uw3 * bz3);
    }
}

// ---------------- init1: build Bc (one-time scattered gather) ----------------
// grid = (NBLK1, K) = 2048 blocks of 256, 1 e per thread; no occupancy cap
__global__ void init1_kernel(const float* __restrict__ Bm) {
    int k = blockIdx.y;
    size_t kE = (size_t)k * E;
    int tid = threadIdx.x;
    int e = blockIdx.x * 256 + tid;

    uint2 pk = *(const uint2*)(g_nzpk + e * MAXNZ);
    int cnt  = g_cnt[e];
    const float* __restrict__ Brow = Bm + (kE + e) * K;
    unsigned pw0 = pk.x, pw1 = pk.y;
    float v[HOT];
#pragma unroll
    for (int i = 0; i < HOT; i++) {
        int j = ((i < 4 ? pw0 : pw1) >> ((i & 3) * 8)) & 0xFF;
        v[i] = (i < cnt && j != k) ? __ldg(Brow + j) : 0.0f;
    }
    float4* dst = (float4*)(g_Bc + (kE + e) * HOT);
    dst[0] = make_float4(v[0], v[1], v[2], v[3]);
    dst[1] = make_float4(v[4], v[5], v[6], v[7]);
}

// ---------------- big step kernel: KB k's per block, per-e work amortized ----------------
// grid = (NBLK, K/KB) = (16, 64) = 1024 blocks of 256; 1 e per thread
__global__ __launch_bounds__(256) void big_kernel(const float* __restrict__ Bm,
                                                  float* __restrict__ out,
                                                  int step) {
    int k0 = blockIdx.y * KB;
    int tid = threadIdx.x;
    int e = blockIdx.x * 256 + tid;

    __shared__ float2 s_ud[K];   // (u, dv)
    if (tid < K) {
        float u = g_u[tid];
        float dv = u - 0.5f;
        dv = (fabsf(dv) > THRESHOLD) ? dv : 0.0f;
        s_ud[tid] = make_float2(u, dv);
    }
    __syncthreads();

    // ---- per-e work (shared across KB k's) ----
    uint2 pk  = *(const uint2*)(g_nzpk + e * MAXNZ);
    int cnt   = g_cnt[e];
    float4 cc = g_cc[e];
    unsigned pw0 = pk.x, pw1 = pk.y;

    float su = 0.0f;
    float dv[HOT];
#pragma unroll
    for (int i = 0; i < HOT; i++) {
        int j = ((i < 4 ? pw0 : pw1) >> ((i & 3) * 8)) & 0xFF;
        float2 ud = s_ud[j];
        su   += (i < cnt) ? ud.x : 0.0f;
        dv[i] = ud.y;               // Bc pad entries are 0, mask not needed for dot
    }
    if (cnt > HOT) {                // rare tail: finish su
        const uint4* pkp = (const uint4*)(g_nzpk + e * MAXNZ);
        uint4 p0 = pkp[0], p1 = pkp[1];
        unsigned pw[8] = {p0.x, p0.y, p0.z, p0.w, p1.x, p1.y, p1.z, p1.w};
        for (int i = HOT; i < cnt; i++) {
            int j = (pw[i >> 2] >> ((i & 3) * 8)) & 0xFF;
            su += s_ud[j].x;
        }
    }
    float t  = cc.z - su * cc.w;
    float Ic = sigm_neg(cc.x + cc.y * __expf(-t * t));

    // ---- per-k work ----
    float acc[KB];
#pragma unroll
    for (int kk = 0; kk < KB; kk++) {
        int k = k0 + kk;
        size_t kE = (size_t)k * E;
        const float4* bc = (const float4*)(g_Bc + (kE + e) * HOT);
        float4 b0 = bc[0], b1 = bc[1];
        float2 a  = g_a12[kE + e];
        float dot = b0.x * dv[0] + b0.y * dv[1] + b0.z * dv[2] + b0.w * dv[3]
                  + b1.x * dv[4] + b1.y * dv[5] + b1.z * dv[6] + b1.w * dv[7];
        if (cnt > HOT) {            // rare tail: finish dot
            const uint4* pkp = (const uint4*)(g_nzpk + e * MAXNZ);
            uint4 p0 = pkp[0], p1 = pkp[1];
            unsigned pw[8] = {p0.x, p0.y, p0.z, p0.w, p1.x, p1.y, p1.z, p1.w};
            const float* __restrict__ Brow = Bm + (kE + e) * K;
            for (int i = HOT; i < cnt; i++) {
                int j = (pw[i >> 2] >> ((i & 3) * 8)) & 0xFF;
                if (j != k) dot += __ldg(Brow + j) * s_ud[j].y;
            }
        }
        float gkc = sigm_neg(dot) - 1.0f;
        acc[kk] = Ic * (a.x * gkc + a.y);
    }

    // ---- deterministic block reductions (one per k) ----
    __shared__ float warpacc[KB][8];
    int w = tid >> 5, l = tid & 31;
#pragma unroll
    for (int kk = 0; kk < KB; kk++) {
        float v = acc[kk];
        v += __shfl_xor_sync(0xFFFFFFFFu, v, 16);
        v += __shfl_xor_sync(0xFFFFFFFFu, v, 8);
        v += __shfl_xor_sync(0xFFFFFFFFu, v, 4);
        v += __shfl_xor_sync(0xFFFFFFFFu, v, 2);
        v += __shfl_xor_sync(0xFFFFFFFFu, v, 1);
        if (l == 0) warpacc[kk][w] = v;
    }
    __syncthreads();

    __shared__ bool is_last;
    if (tid < KB) {
        float s = 0.0f;
#pragma unroll
        for (int i = 0; i < 8; i++) s += warpacc[tid][i];
        g_partial[(k0 + tid) * NBLK + blockIdx.x] = s;
    }
    __syncthreads();
    if (tid == 0) {
        __threadfence();
        unsigned t2 = atomicAdd(&g_done[step], 1u);
        is_last = (t2 == (unsigned)(NB_TOTAL - 1));
    }
    __syncthreads();
    if (!is_last) return;
    __threadfence();

    // ---- tiny fused epilogue (one block) ----
    __shared__ float red[K];
    if (tid < K) {
        float s = 0.0f;
#pragma unroll
        for (int c = 0; c < NBLK; c++) s += g_partial[tid * NBLK + c];
        float u_old = g_u[tid];
        float u_new = sigm_neg(s);
        float un = g_upd[tid] ? u_new : u_old;
        float ddf = un - u_old;
        red[tid] = ddf * ddf;
        g_u[tid] = un;
        if (step == NUM_UPDATE - 2) out[K + tid] = un;  // state_2nd_last
        if (step == NUM_UPDATE - 1) out[tid]     = un;  // state_last
    }
    __syncthreads();
#pragma unroll
    for (int off = 64; off > 0; off >>= 1) {
        if (tid < off && tid + off < K) red[tid] += red[tid + off];
        __syncthreads();
    }
    if (tid == 0) out[2 * K + M + step] = sqrtf(red[0]);
}

// ---------------- final predict ----------------
__global__ void predict_kernel(const float* __restrict__ dd,
                               const float* __restrict__ alpha,
                               const float* __restrict__ gamma_e,
                               const int* __restrict__ ex_id,
                               float* __restrict__ out) {
    __shared__ float s_u[K];
    int tid = threadIdx.x;
    if (tid < K) s_u[tid] = g_u[tid];
    __syncthreads();

    int m = blockIdx.x * 256 + tid;
    if (m < M) {
        int e = ex_id[m];
        const uint4* pkp = (const uint4*)(g_nzpk + e * MAXNZ);
        uint4 p0 = pkp[0], p1 = pkp[1];
        unsigned pw[8] = {p0.x, p0.y, p0.z, p0.w, p1.x, p1.y, p1.z, p1.w};
        int cnt = g_cnt[e];
        float accv = 0.0f;
        for (int i = 0; i < cnt; i++) {
            int j = (pw[i >> 2] >> ((i & 3) * 8)) & 0xFF;
            accv += s_u[j];
        }
        float Ukse = accv / dd[e] - 0.5f;
        out[2 * K + m] = sigm_neg(alpha[e] * Ukse + gamma_e[e]);
    }
}

// ---------------- launch ----------------
extern "C" void kernel_launch(void* const* d_in, const int* in_sizes, int n_in,
                              void* d_out, int out_size) {
    const float* U       = (const float*)d_in[0];
    const float* W       = (const float*)d_in[1];
    const float* beta1   = (const float*)d_in[2];
    const float* beta2   = (const float*)d_in[3];
    const float* Bm      = (const float*)d_in[4];
    const float* gs      = (const float*)d_in[5];
    const float* A_emb   = (const float*)d_in[6];
    const float* gamma_c = (const float*)d_in[7];
    const float* gamma_e = (const float*)d_in[8];
    const float* alpha   = (const float*)d_in[9];
    const float* score   = (const float*)d_in[10];
    const float* user    = (const float*)d_in[11];
    const float* q_kn    = (const float*)d_in[12];
    const float* d       = (const float*)d_in[13];
    const int*   stu_id  = (const int*)d_in[14];
    const int*   kn_id   = (const int*)d_in[15];
    const int*   ex_id   = (const int*)d_in[16];
    float* out = (float*)d_out;

    init0_kernel<<<E / 8, 256>>>(q_kn, U, stu_id, kn_id, gamma_c, d, score,
                                 beta2, gs, A_emb);
    init0b_kernel<<<256, 256>>>(beta1, W, user);
    init1_kernel<<<dim3(NBLK1, K), 256>>>(Bm);
    for (int step = 0; step < NUM_UPDATE; ++step) {
        big_kernel<<<dim3(NBLK, K / KB), 256>>>(Bm, out, step);
    }
    predict_kernel<<<(M + 255) / 256, 256>>>(d, alpha, gamma_e, ex_id, out);
}

// round 8
// speedup vs baseline: 1.1999x; 1.1999x over previous
#include <cuda_runtime.h>
#include <math.h>

#define K 128
#define E 4096
#define M 512
#define NUM_UPDATE 3
#define THRESHOLD 0.05f
#define HOT 8
#define MAXNZ 32
#define NBLK 16                       // e-chunks per step grid
#define NB_TOTAL (NBLK * K)           // 2048 blocks

// ---------------- device scratch ----------------
__device__ __align__(16) unsigned char g_nzpk[E * MAXNZ];
__device__ unsigned char g_cnt[E];
__device__ float4 g_cc[E];                    // (c0, c1, score, 1/d) per e
__device__ float  g_bz[E];                    // beta2 * Zc
__device__ float2 g_a12[(size_t)K * E];       // (uw*beta1, uw*bz)
__device__ float  g_Bc[(size_t)K * E * HOT];  // gathered B, diag/pad zeroed
__device__ float  g_u[K];
__device__ int    g_upd[K];
__device__ float  g_partial[K * NBLK];
__device__ unsigned g_done[NUM_UPDATE];

__device__ __forceinline__ float sigm_neg(float x) {
    return __fdividef(1.0f, 1.0f + __expf(x));  // sigmoid(-x)
}

// ---------------- init0: nz lists, per-e constants, u0, upd ----------------
// grid = E/8 = 512 blocks of 256 (warp per e)
__global__ void init0_kernel(const float* __restrict__ q_kn,
                             const float* __restrict__ U,
                             const int* __restrict__ stu_id,
                             const int* __restrict__ kn_id,
                             const float* __restrict__ gamma_c,
                             const float* __restrict__ dd,
                             const float* __restrict__ score,
                             const float* __restrict__ beta2,
                             const float* __restrict__ gs,
                             const float* __restrict__ A_emb) {
    int tid = threadIdx.x;
    int w = tid >> 5, l = tid & 31;
    int e = blockIdx.x * 8 + w;

    int base = 0;
#pragma unroll
    for (int r = 0; r < 4; r++) {
        int j = r * 32 + l;
        float q = q_kn[(size_t)e * K + j];
        unsigned m = __ballot_sync(0xFFFFFFFFu, q != 0.0f);
        if (q != 0.0f) {
            int pos = base + __popc(m & ((1u << l) - 1u));
            if (pos < MAXNZ) g_nzpk[e * MAXNZ + pos] = (unsigned char)j;
        }
        base += __popc(m);
    }
    if (l == 0) {
        g_cnt[e] = (unsigned char)(base < MAXNZ ? base : MAXNZ);
        float invd = 1.0f / dd[e];
        float sc   = score[e];
        float x  = (gamma_c[e] * invd) * (sc - 0.5f);
        g_bz[e]  = beta2[e] * (sigm_neg(x) - 0.5f);
        float c0 = A_emb[3 * e + 0] * (1.0f - gs[2 * e + 0])
                 + A_emb[3 * e + 1] * (1.0f - gs[2 * e + 1]);
        float c1 = A_emb[3 * e + 2];
        g_cc[e] = make_float4(c0, c1, sc, invd);
    }

    if (blockIdx.x == 0) {
        if (tid < NUM_UPDATE) g_done[tid] = 0u;
        if (tid < K) {
            g_u[tid] = U[(size_t)stu_id[0] * K + tid];
            g_upd[tid] = 0;
        }
        __syncthreads();
        if (tid < K) {
            int kn = kn_id[tid];
            if (kn >= 0 && kn < K) g_upd[kn] = 1;
        }
    }
}

// ---------------- big step kernel ----------------
// grid = (NBLK, K) = (16, 128) = 2048 blocks of 256; 1 e per thread.
// GATHER (step 0): reads B scattered, computes dot, AND writes Bc + a12 for steps 1,2.
// !GATHER (steps 1,2): reads precomputed Bc + a12.
template <bool GATHER>
__global__ __launch_bounds__(256) void big_kernel(const float* __restrict__ Bm,
                                                  const float* __restrict__ beta1,
                                                  const float* __restrict__ W,
                                                  const float* __restrict__ user,
                                                  float* __restrict__ out,
                                                  int step) {
    int k = blockIdx.y;
    size_t kE = (size_t)k * E;
    int tid = threadIdx.x;
    int e = blockIdx.x * 256 + tid;

    __shared__ float2 s_ud[K];   // (u, dv)
    if (tid < K) {
        float u = g_u[tid];
        float dv = u - 0.5f;
        dv = (fabsf(dv) > THRESHOLD) ? dv : 0.0f;
        s_ud[tid] = make_float2(u, dv);
    }
    __syncthreads();

    uint2 pk  = *(const uint2*)(g_nzpk + e * MAXNZ);
    int cnt   = g_cnt[e];
    float4 cc = g_cc[e];
    unsigned pw0 = pk.x, pw1 = pk.y;

    float su = 0.0f, dot = 0.0f;
    float2 a;

    if (GATHER) {
        const float* __restrict__ Brow = Bm + (kE + e) * K;
        float bc[HOT];
#pragma unroll
        for (int i = 0; i < HOT; i++) {
            int j = ((i < 4 ? pw0 : pw1) >> ((i & 3) * 8)) & 0xFF;
            bool act = (i < cnt) && (j != k);
            bc[i] = act ? __ldg(Brow + j) : 0.0f;
            float2 ud = s_ud[j];
            su  += (i < cnt) ? ud.x : 0.0f;
            dot += bc[i] * ud.y;
        }
        // persist Bc for steps 1,2
        float4* dst = (float4*)(g_Bc + (kE + e) * HOT);
        dst[0] = make_float4(bc[0], bc[1], bc[2], bc[3]);
        dst[1] = make_float4(bc[4], bc[5], bc[6], bc[7]);
        // build and persist a12
        float uw = user[kE + e] * W[kE + e];
        a = make_float2(uw * beta1[kE + e], uw * g_bz[e]);
        g_a12[kE + e] = a;
    } else {
        const float4* bc = (const float4*)(g_Bc + (kE + e) * HOT);
        float4 b0 = bc[0], b1 = bc[1];
        a = g_a12[kE + e];
        float dv[HOT];
#pragma unroll
        for (int i = 0; i < HOT; i++) {
            int j = ((i < 4 ? pw0 : pw1) >> ((i & 3) * 8)) & 0xFF;
            float2 ud = s_ud[j];
            su   += (i < cnt) ? ud.x : 0.0f;
            dv[i] = ud.y;
        }
        dot = b0.x * dv[0] + b0.y * dv[1] + b0.z * dv[2] + b0.w * dv[3]
            + b1.x * dv[4] + b1.y * dv[5] + b1.z * dv[6] + b1.w * dv[7];
    }

    if (cnt > HOT) {   // rare tail (both variants): finish su and dot via direct gather
        const uint4* pkp = (const uint4*)(g_nzpk + e * MAXNZ);
        uint4 p0 = pkp[0], p1 = pkp[1];
        unsigned pw[8] = {p0.x, p0.y, p0.z, p0.w, p1.x, p1.y, p1.z, p1.w};
        const float* __restrict__ Brow = Bm + (kE + e) * K;
        for (int i = HOT; i < cnt; i++) {
            int j = (pw[i >> 2] >> ((i & 3) * 8)) & 0xFF;
            float2 ud = s_ud[j];
            su += ud.x;
            if (j != k) dot += __ldg(Brow + j) * ud.y;
        }
    }

    float t   = cc.z - su * cc.w;
    float Ic  = sigm_neg(cc.x + cc.y * __expf(-t * t));
    float gkc = sigm_neg(dot) - 1.0f;
    float acc = Ic * (a.x * gkc + a.y);

    // deterministic block reduction
    __shared__ float warpacc[8];
    int w = tid >> 5, l = tid & 31;
    acc += __shfl_xor_sync(0xFFFFFFFFu, acc, 16);
    acc += __shfl_xor_sync(0xFFFFFFFFu, acc, 8);
    acc += __shfl_xor_sync(0xFFFFFFFFu, acc, 4);
    acc += __shfl_xor_sync(0xFFFFFFFFu, acc, 2);
    acc += __shfl_xor_sync(0xFFFFFFFFu, acc, 1);
    if (l == 0) warpacc[w] = acc;
    __syncthreads();

    __shared__ bool is_last;
    if (tid == 0) {
        float s = 0.0f;
#pragma unroll
        for (int i = 0; i < 8; i++) s += warpacc[i];
        g_partial[k * NBLK + blockIdx.x] = s;
        __threadfence();
        unsigned t2 = atomicAdd(&g_done[step], 1u);
        is_last = (t2 == (unsigned)(NB_TOTAL - 1));
    }
    __syncthreads();
    if (!is_last) return;
    __threadfence();

    // ---- tiny fused epilogue (one block) ----
    __shared__ float red[K];
    if (tid < K) {
        float s = 0.0f;
#pragma unroll
        for (int c = 0; c < NBLK; c++) s += g_partial[tid * NBLK + c];
        float u_old = g_u[tid];
        float u_new = sigm_neg(s);
        float un = g_upd[tid] ? u_new : u_old;
        float ddf = un - u_old;
        red[tid] = ddf * ddf;
        g_u[tid] = un;
        if (step == NUM_UPDATE - 2) out[K + tid] = un;  // state_2nd_last
        if (step == NUM_UPDATE - 1) out[tid]     = un;  // state_last
    }
    __syncthreads();
#pragma unroll
    for (int off = 64; off > 0; off >>= 1) {
        if (tid < off && tid + off < K) red[tid] += red[tid + off];
        __syncthreads();
    }
    if (tid == 0) out[2 * K + M + step] = sqrtf(red[0]);
}

// ---------------- final predict ----------------
__global__ void predict_kernel(const float* __restrict__ dd,
                               const float* __restrict__ alpha,
                               const float* __restrict__ gamma_e,
                               const int* __restrict__ ex_id,
                               float* __restrict__ out) {
    __shared__ float s_u[K];
    int tid = threadIdx.x;
    if (tid < K) s_u[tid] = g_u[tid];
    __syncthreads();

    int m = blockIdx.x * 256 + tid;
    if (m < M) {
        int e = ex_id[m];
        const uint4* pkp = (const uint4*)(g_nzpk + e * MAXNZ);
        uint4 p0 = pkp[0], p1 = pkp[1];
        unsigned pw[8] = {p0.x, p0.y, p0.z, p0.w, p1.x, p1.y, p1.z, p1.w};
        int cnt = g_cnt[e];
        float accv = 0.0f;
        for (int i = 0; i < cnt; i++) {
            int j = (pw[i >> 2] >> ((i & 3) * 8)) & 0xFF;
            accv += s_u[j];
        }
        float Ukse = accv / dd[e] - 0.5f;
        out[2 * K + m] = sigm_neg(alpha[e] * Ukse + gamma_e[e]);
    }
}

// ---------------- launch ----------------
extern "C" void kernel_launch(void* const* d_in, const int* in_sizes, int n_in,
                              void* d_out, int out_size) {
    const float* U       = (const float*)d_in[0];
    const float* W       = (const float*)d_in[1];
    const float* beta1   = (const float*)d_in[2];
    const float* beta2   = (const float*)d_in[3];
    const float* Bm      = (const float*)d_in[4];
    const float* gs      = (const float*)d_in[5];
    const float* A_emb   = (const float*)d_in[6];
    const float* gamma_c = (const float*)d_in[7];
    const float* gamma_e = (const float*)d_in[8];
    const float* alpha   = (const float*)d_in[9];
    const float* score   = (const float*)d_in[10];
    const float* user    = (const float*)d_in[11];
    const float* q_kn    = (const float*)d_in[12];
    const float* d       = (const float*)d_in[13];
    const int*   stu_id  = (const int*)d_in[14];
    const int*   kn_id   = (const int*)d_in[15];
    const int*   ex_id   = (const int*)d_in[16];
    float* out = (float*)d_out;

    init0_kernel<<<E / 8, 256>>>(q_kn, U, stu_id, kn_id, gamma_c, d, score,
                                 beta2, gs, A_emb);
    big_kernel<true><<<dim3(NBLK, K), 256>>>(Bm, beta1, W, user, out, 0);
    big_kernel<false><<<dim3(NBLK, K), 256>>>(Bm, beta1, W, user, out, 1);
    big_kernel<false><<<dim3(NBLK, K), 256>>>(Bm, beta1, W, user, out, 2);
    predict_kernel<<<(M + 255) / 256, 256>>>(d, alpha, gamma_e, ex_id, out);
}